// round 2
// baseline (speedup 1.0000x reference)
#include <cuda_runtime.h>

#define IMG 512
#define TW 64
#define TH 32
#define KS 11
#define HALO 5
#define COLS (TW + 2*HALO)   /* 74 */
#define ROWS (TH + 2*HALO)   /* 42 */
#define S2 75                /* float2 stride (odd -> conflict-free LDS.64 across rows) */
#define NPAIR 37             /* u64 columns for paired xy planes (odd stride) */
#define NTHREADS 256
#define NBLK (8*16*64)
/* smem: s_in 42*75*8 + s_v1 32*75*8 + s_v2 32*75*8 + s_pz 42*37*8 + s_v3 32*37*8 */
#define SMEM_BYTES (ROWS*S2*8 + TH*S2*8 + TH*S2*8 + ROWS*NPAIR*8 + TH*NPAIR*8)

typedef unsigned long long u64;

__device__ double g_accum = 0.0;
__device__ unsigned int g_done = 0;

__device__ __forceinline__ u64 pack2(float x, float y) {
    u64 r; asm("mov.b64 %0, {%1,%2};" : "=l"(r) : "f"(x), "f"(y)); return r;
}
__device__ __forceinline__ void unpack2(u64 v, float& x, float& y) {
    asm("mov.b64 {%0,%1}, %2;" : "=f"(x), "=f"(y) : "l"(v));
}
__device__ __forceinline__ u64 fma2(u64 a, u64 b, u64 c) {
    u64 d; asm("fma.rn.f32x2 %0, %1, %2, %3;" : "=l"(d) : "l"(a), "l"(b), "l"(c)); return d;
}
__device__ __forceinline__ u64 mul2(u64 a, u64 b) {
    u64 d; asm("mul.rn.f32x2 %0, %1, %2;" : "=l"(d) : "l"(a), "l"(b)); return d;
}

extern __shared__ float2 smem_dyn[];

__global__ __launch_bounds__(NTHREADS, 2)
void ssim_fused_kernel(const float* __restrict__ x, const float* __restrict__ y,
                       const float* __restrict__ kern, float* __restrict__ out) {
    float2* s_in = smem_dyn;                         // [ROWS][S2] (x,y)
    float2* s_v1 = s_in + ROWS * S2;                 // [TH][S2]   (sx,sy)
    float2* s_v2 = s_v1 + TH * S2;                   // [TH][S2]   (sxx,syy)
    u64*    s_pz = (u64*)(s_v2 + TH * S2);           // [ROWS][NPAIR] pxy input, col-paired
    u64*    s_v3 = s_pz + ROWS * NPAIR;              // [TH][NPAIR]   sxy vsum, col-paired

    __shared__ float s_wraw[22];

    const int tid = threadIdx.x;
    const int plane = blockIdx.z;       // 64 planes = 32 batch * 2 chan (NCHW)
    const int ch = plane & 1;
    const int oh0 = blockIdx.y * TH;
    const int ow0 = blockIdx.x * TW;
    const float* xp = x + (size_t)plane * IMG * IMG;
    const float* yp = y + (size_t)plane * IMG * IMG;

    // ---- weights: rank-1 factor reconstruction from 2D gaussian (22 threads) ----
    if (tid < 22) {
        const float* kc = kern + ch * KS * KS;
        float s = 0.f;
        if (tid < 11) {
            int i = tid;
            #pragma unroll
            for (int j = 0; j < KS; j++) s += kc[i * KS + j];   // row sums
        } else {
            int i = tid - 11;
            #pragma unroll
            for (int j = 0; j < KS; j++) s += kc[j * KS + i];   // col sums
        }
        s_wraw[tid] = s;
    }

    // ---- stage 0: load tile (zero-padded halo), also precompute pxy plane ----
    for (int idx = tid; idx < ROWS * COLS; idx += NTHREADS) {
        int tr = idx / COLS, tc = idx - tr * COLS;
        int gr = oh0 + tr - HALO, gc = ow0 + tc - HALO;
        float vx = 0.f, vy = 0.f;
        if ((unsigned)gr < (unsigned)IMG && (unsigned)gc < (unsigned)IMG) {
            int off = gr * IMG + gc;
            vx = __ldg(xp + off); vy = __ldg(yp + off);
        }
        s_in[tr * S2 + tc] = make_float2(vx, vy);
        ((float*)s_pz)[tr * (2 * NPAIR) + tc] = vx * vy;
    }

    __syncthreads();

    // ---- per-thread weight registers ----
    float T = 0.f;
    #pragma unroll
    for (int k = 0; k < KS; k++) T += s_wraw[k];
    float invT = 1.0f / T;
    u64 wv2[KS], wh2[KS]; float whs[KS];
    #pragma unroll
    for (int k = 0; k < KS; k++) {
        float wv = s_wraw[k];
        wv2[k] = pack2(wv, wv);
        whs[k] = s_wraw[11 + k] * invT;
        wh2[k] = pack2(whs[k], whs[k]);
    }

    // ---- stage 1: vertical conv ----
    // task type A (296): one column, 8 output rows, streams (x,y) & (x²,y²) packed
    // task type B (148): one column PAIR, 8 output rows, xy stream packed across cols
    for (int t = tid; t < 296 + 148; t += NTHREADS) {
        if (t < 296) {
            int col = t % COLS;
            int rg = (t / COLS) * 8;
            u64 a1[8], a2[8];
            #pragma unroll
            for (int i = 0; i < 8; i++) { a1[i] = 0ull; a2[i] = 0ull; }
            #pragma unroll
            for (int tt = 0; tt < 18; tt++) {
                u64 u = *reinterpret_cast<const u64*>(&s_in[(rg + tt) * S2 + col]);
                u64 v = mul2(u, u);
                #pragma unroll
                for (int i = 0; i < 8; i++) {
                    int k = tt - i;
                    if (k >= 0 && k < KS) {
                        a1[i] = fma2(wv2[k], u, a1[i]);
                        a2[i] = fma2(wv2[k], v, a2[i]);
                    }
                }
            }
            #pragma unroll
            for (int i = 0; i < 8; i++) {
                *reinterpret_cast<u64*>(&s_v1[(rg + i) * S2 + col]) = a1[i];
                *reinterpret_cast<u64*>(&s_v2[(rg + i) * S2 + col]) = a2[i];
            }
        } else {
            int tb = t - 296;
            int cp = tb % NPAIR;
            int rg = (tb / NPAIR) * 8;
            u64 a3[8];
            #pragma unroll
            for (int i = 0; i < 8; i++) a3[i] = 0ull;
            #pragma unroll
            for (int tt = 0; tt < 18; tt++) {
                u64 p = s_pz[(rg + tt) * NPAIR + cp];
                #pragma unroll
                for (int i = 0; i < 8; i++) {
                    int k = tt - i;
                    if (k >= 0 && k < KS) a3[i] = fma2(wv2[k], p, a3[i]);
                }
            }
            #pragma unroll
            for (int i = 0; i < 8; i++) s_v3[(rg + i) * NPAIR + cp] = a3[i];
        }
    }

    __syncthreads();

    // ---- stage 2: horizontal conv, 8 consecutive px per thread ----
    const int row = tid & 31;
    const int c0 = (tid >> 5) * 8;
    const int cp0 = c0 >> 1;

    // xy vsums for cols [c0, c0+17]: 9 paired LDS.64
    float g3[18];
    #pragma unroll
    for (int m = 0; m < 9; m++) {
        u64 g = s_v3[row * NPAIR + cp0 + m];
        unpack2(g, g3[2 * m], g3[2 * m + 1]);
    }

    u64 h1[8], h2[8]; float h3[8];
    #pragma unroll
    for (int p = 0; p < 8; p++) { h1[p] = 0ull; h2[p] = 0ull; h3[p] = 0.f; }
    #pragma unroll
    for (int j = 0; j < 18; j++) {
        u64 b1 = *reinterpret_cast<const u64*>(&s_v1[row * S2 + c0 + j]);
        u64 b2 = *reinterpret_cast<const u64*>(&s_v2[row * S2 + c0 + j]);
        float b3 = g3[j];
        #pragma unroll
        for (int p = 0; p < 8; p++) {
            int k = j - p;
            if (k >= 0 && k < KS) {
                h1[p] = fma2(wh2[k], b1, h1[p]);
                h2[p] = fma2(wh2[k], b2, h2[p]);
                h3[p] = fmaf(whs[k], b3, h3[p]);
            }
        }
    }

    // ---- epilogue: SSIM per pixel + local sum ----
    float lsum = 0.f;
    const float C1 = 1e-4f, C2 = 9e-4f;
    #pragma unroll
    for (int p = 0; p < 8; p++) {
        float mux, muy; unpack2(h1[p], mux, muy);
        float ex2, ey2; unpack2(h2[p], ex2, ey2);
        float exy = h3[p];
        float mux2 = mux * mux, muy2 = muy * muy, muxy = mux * muy;
        float sx = ex2 - mux2, sy = ey2 - muy2, sxy = exy - muxy;
        float num = (2.f * muxy + C1) * (2.f * sxy + C2);
        float den = (mux2 + muy2 + C1) * (sx + sy + C2);
        lsum += __fdividef(num, den);
    }

    // ---- reduction: warp shuffle -> block -> one double atomic -> last-block finalize ----
    #pragma unroll
    for (int o = 16; o > 0; o >>= 1) lsum += __shfl_xor_sync(0xffffffffu, lsum, o);
    __shared__ float wsum[NTHREADS / 32];
    if ((tid & 31) == 0) wsum[tid >> 5] = lsum;
    __syncthreads();
    if (tid == 0) {
        float b = 0.f;
        #pragma unroll
        for (int w = 0; w < NTHREADS / 32; w++) b += wsum[w];
        atomicAdd(&g_accum, (double)b);
        __threadfence();
        unsigned prev = atomicAdd(&g_done, 1u);
        if (prev == (unsigned)(NBLK - 1)) {
            __threadfence();
            double total = atomicAdd(&g_accum, 0.0);  // all blocks' adds visible
            out[0] = 1.0f - (float)(total * (1.0 / (32.0 * 2.0 * 512.0 * 512.0)));
            // reset state for next graph replay (stream-ordered visibility)
            *(volatile double*)&g_accum = 0.0;
            __threadfence();
            *(volatile unsigned*)&g_done = 0u;
        }
    }
}

extern "C" void kernel_launch(void* const* d_in, const int* in_sizes, int n_in,
                              void* d_out, int out_size) {
    const float* x = (const float*)d_in[0];
    const float* y = (const float*)d_in[1];
    const float* kern = (const float*)d_in[2];
    float* out = (float*)d_out;

    cudaFuncSetAttribute(ssim_fused_kernel, cudaFuncAttributeMaxDynamicSharedMemorySize, SMEM_BYTES);

    dim3 grid(IMG / TW, IMG / TH, 64);
    ssim_fused_kernel<<<grid, NTHREADS, SMEM_BYTES>>>(x, y, kern, out);
}

// round 3
// speedup vs baseline: 2.5446x; 2.5446x over previous
#include <cuda_runtime.h>

#define IMG 512
#define TW 64
#define TH 32
#define KS 11
#define HALO 5
#define COLS 74              /* TW + 2*HALO */
#define S2 75                /* float2/float row stride (odd -> conflict-free) */
#define RG 4                 /* output rows per vertical task */
#define NROWG (TH/RG)        /* 8 */
#define NTASK (COLS*NROWG)   /* 592 */
#define NTHREADS 256
#define SMEM_BYTES (TH*S2*8*2 + TH*S2*4)   /* 48000 B -> 4 CTAs/SM */

typedef unsigned long long u64;

__device__ double g_accum;
__device__ float g_wv[2][KS];
__device__ float g_wh[2][KS];

__device__ __forceinline__ u64 pack2(float x, float y) {
    u64 r; asm("mov.b64 %0, {%1,%2};" : "=l"(r) : "f"(x), "f"(y)); return r;
}
__device__ __forceinline__ void unpack2(u64 v, float& x, float& y) {
    asm("mov.b64 {%0,%1}, %2;" : "=f"(x), "=f"(y) : "l"(v));
}
__device__ __forceinline__ u64 fma2(u64 a, u64 b, u64 c) {
    u64 d; asm("fma.rn.f32x2 %0, %1, %2, %3;" : "=l"(d) : "l"(a), "l"(b), "l"(c)); return d;
}
__device__ __forceinline__ u64 mul2(u64 a, u64 b) {
    u64 d; asm("mul.rn.f32x2 %0, %1, %2;" : "=l"(d) : "l"(a), "l"(b)); return d;
}

/* Gaussian weight index with symmetry w[k] == w[10-k] (bit-exact: k2 = g outer g) */
#define WIDX(k) ((k) < 6 ? (k) : 10 - (k))

// Rank-1 factor reconstruction, parallel: warp 0 -> ch 0, warp 1 -> ch 1.
__global__ void prep_kernel(const float* __restrict__ kern) {
    int tid = threadIdx.x;
    if (tid == 0) g_accum = 0.0;
    if (tid < 64) {
        int ch = tid >> 5, lane = tid & 31;
        const float* kc = kern + ch * KS * KS;
        float s = 0.f;
        if (lane < KS) {                      // row sums
            #pragma unroll
            for (int j = 0; j < KS; j++) s += kc[lane * KS + j];
        } else if (lane < 2 * KS) {           // col sums
            int i = lane - KS;
            #pragma unroll
            for (int j = 0; j < KS; j++) s += kc[j * KS + i];
        }
        float contrib = (lane < KS) ? s : 0.f;
        #pragma unroll
        for (int o = 16; o > 0; o >>= 1) contrib += __shfl_xor_sync(0xffffffffu, contrib, o);
        /* contrib == T (kernel total) in every lane */
        if (lane < KS)           g_wv[ch][lane] = s;
        else if (lane < 2 * KS)  g_wh[ch][lane - KS] = s / contrib;
    }
}

extern __shared__ float2 smem_dyn[];

__global__ __launch_bounds__(NTHREADS, 4)
void ssim_main(const float* __restrict__ x, const float* __restrict__ y) {
    float2* s_v1 = smem_dyn;                 // [TH][S2] (sx,sy)
    float2* s_v2 = s_v1 + TH * S2;           // [TH][S2] (sxx,syy)
    float*  s_v3 = (float*)(s_v2 + TH * S2); // [TH][S2] sxy

    const int tid = threadIdx.x;
    const int plane = blockIdx.z;            // 64 = 32 batch * 2 chan (NCHW)
    const int ch = plane & 1;
    const int oh0 = blockIdx.y * TH;
    const int ow0 = blockIdx.x * TW;
    const float* xp = x + (size_t)plane * IMG * IMG;
    const float* yp = y + (size_t)plane * IMG * IMG;

    u64 wv2[6];
    #pragma unroll
    for (int k = 0; k < 6; k++) { float w = __ldg(&g_wv[ch][k]); wv2[k] = pack2(w, w); }

    // ---- stage 1: vertical conv straight from global (no input tile) ----
    for (int t = tid; t < NTASK; t += NTHREADS) {
        int rgi = t / COLS;
        int col = t - rgi * COLS;
        int rg = rgi * RG;
        int gc = ow0 + col - HALO;
        bool colok = (unsigned)gc < (unsigned)IMG;
        int r0 = oh0 + rg - HALO;
        const float* xb = xp + (ptrdiff_t)r0 * IMG + gc;
        const float* yb = yp + (ptrdiff_t)r0 * IMG + gc;

        u64 a1[RG], a2[RG]; float a3[RG];
        #pragma unroll
        for (int i = 0; i < RG; i++) { a1[i] = 0ull; a2[i] = 0ull; a3[i] = 0.f; }

        #pragma unroll
        for (int tt = 0; tt < RG + KS - 1; tt++) {   // 14 input rows
            int gr = r0 + tt;
            float vx = 0.f, vy = 0.f;
            if (colok && (unsigned)gr < (unsigned)IMG) {
                vx = __ldg(xb + tt * IMG);
                vy = __ldg(yb + tt * IMG);
            }
            u64 u = pack2(vx, vy);
            u64 v = mul2(u, u);
            float pxy = vx * vy;
            #pragma unroll
            for (int i = 0; i < RG; i++) {
                int k = tt - i;
                if (k >= 0 && k < KS) {
                    int wi = WIDX(k);
                    a1[i] = fma2(wv2[wi], u, a1[i]);
                    a2[i] = fma2(wv2[wi], v, a2[i]);
                    a3[i] = fmaf(__uint_as_float((unsigned)(wv2[wi] & 0xffffffffull)), pxy, a3[i]);
                }
            }
        }
        #pragma unroll
        for (int i = 0; i < RG; i++) {
            *reinterpret_cast<u64*>(&s_v1[(rg + i) * S2 + col]) = a1[i];
            *reinterpret_cast<u64*>(&s_v2[(rg + i) * S2 + col]) = a2[i];
            s_v3[(rg + i) * S2 + col] = a3[i];
        }
    }

    __syncthreads();

    // ---- stage 2: horizontal conv, two half-tasks of 4 px (low reg pressure) ----
    u64 wh2[6]; float whs[6];
    #pragma unroll
    for (int k = 0; k < 6; k++) { float w = __ldg(&g_wh[ch][k]); whs[k] = w; wh2[k] = pack2(w, w); }

    const int row = tid & 31;      // lanes span rows -> odd stride, conflict-free
    const int c0 = (tid >> 5) * 8;
    const float C1 = 1e-4f, C2 = 9e-4f;
    float lsum = 0.f;

    #pragma unroll
    for (int ph = 0; ph < 2; ph++) {
        int cb = c0 + 4 * ph;
        u64 h1[4], h2[4]; float h3[4];
        #pragma unroll
        for (int p = 0; p < 4; p++) { h1[p] = 0ull; h2[p] = 0ull; h3[p] = 0.f; }

        #pragma unroll
        for (int j = 0; j < RG + KS - 1; j++) {      // 14 input cols
            u64 b1 = *reinterpret_cast<const u64*>(&s_v1[row * S2 + cb + j]);
            u64 b2 = *reinterpret_cast<const u64*>(&s_v2[row * S2 + cb + j]);
            float b3 = s_v3[row * S2 + cb + j];
            #pragma unroll
            for (int p = 0; p < 4; p++) {
                int k = j - p;
                if (k >= 0 && k < KS) {
                    int wi = WIDX(k);
                    h1[p] = fma2(wh2[wi], b1, h1[p]);
                    h2[p] = fma2(wh2[wi], b2, h2[p]);
                    h3[p] = fmaf(whs[wi], b3, h3[p]);
                }
            }
        }
        #pragma unroll
        for (int p = 0; p < 4; p++) {
            float mux, muy; unpack2(h1[p], mux, muy);
            float ex2, ey2; unpack2(h2[p], ex2, ey2);
            float exy = h3[p];
            float mux2 = mux * mux, muy2 = muy * muy, muxy = mux * muy;
            float sx = ex2 - mux2, sy = ey2 - muy2, sxy = exy - muxy;
            float num = (2.f * muxy + C1) * (2.f * sxy + C2);
            float den = (mux2 + muy2 + C1) * (sx + sy + C2);
            lsum += __fdividef(num, den);
        }
    }

    // ---- reduction ----
    #pragma unroll
    for (int o = 16; o > 0; o >>= 1) lsum += __shfl_xor_sync(0xffffffffu, lsum, o);
    __shared__ float wsum[NTHREADS / 32];
    if ((tid & 31) == 0) wsum[tid >> 5] = lsum;
    __syncthreads();
    if (tid == 0) {
        float b = 0.f;
        #pragma unroll
        for (int w = 0; w < NTHREADS / 32; w++) b += wsum[w];
        atomicAdd(&g_accum, (double)b);
    }
}

__global__ void finalize_kernel(float* __restrict__ out) {
    if (threadIdx.x == 0) {
        out[0] = 1.0f - (float)(g_accum * (1.0 / (32.0 * 2.0 * 512.0 * 512.0)));
    }
}

extern "C" void kernel_launch(void* const* d_in, const int* in_sizes, int n_in,
                              void* d_out, int out_size) {
    const float* x = (const float*)d_in[0];
    const float* y = (const float*)d_in[1];
    const float* kern = (const float*)d_in[2];
    float* out = (float*)d_out;

    prep_kernel<<<1, 64>>>(kern);
    dim3 grid(IMG / TW, IMG / TH, 64);
    ssim_main<<<grid, NTHREADS, SMEM_BYTES>>>(x, y);
    finalize_kernel<<<1, 32>>>(out);
}